// round 15
// baseline (speedup 1.0000x reference)
#include <cuda_runtime.h>
#include <cuda_bf16.h>
#include <cuda_fp16.h>
#include <math.h>
#include <stdint.h>

#define S_DIM 4
#define B_DIM 4096
#define D_DIM 768
#define K_DIM 8192
#define N_ROWS 16384
#define RPC 16                  // rows per CTA in row passes
#define TOT_ELEMS 134217728LL   // N_ROWS * K_DIM

#define KTOT 2304               // 3 * D_DIM (concatenated split planes)

// ---------------- scratch (device globals; no allocation allowed) ----------------
__device__ float g_logits[(size_t)N_ROWS * K_DIM];   // 512 MB
__device__ __half g_that[(size_t)N_ROWS * K_DIM];    // 256 MB   t~ (fp16)
__device__ float g_inv_norm[N_ROWS];
__device__ float g_c[S_DIM * K_DIM];                 // c-hat (t~ basis), init 1
__device__ float g_d[S_DIM * K_DIM];                 // shift + ln(A1+eps) - 50
__device__ float g_A[S_DIM * K_DIM];
__device__ float g_r[N_ROWS];
__device__ float g_lse[N_ROWS];
// per-mtile column partials written by the GEMM epilogue: [32 mtiles][S][K]
__device__ float g_part_m[32 * S_DIM * K_DIM];
__device__ float g_part_s[32 * S_DIM * K_DIM];
__device__ float g_loss;

// concatenated bf16 split planes:  A3 = [Ah | Ah | Am],  B3 = [Bh | Bm | Bh]
__device__ __nv_bfloat16 g_A3[(size_t)N_ROWS * KTOT];   // 75.5 MB
__device__ __nv_bfloat16 g_B3[(size_t)K_DIM * KTOT];    // 37.7 MB

// ---------------- helpers ---------------------------------------------------------
__device__ __forceinline__ uint32_t smem_u32(const void* p) {
    uint32_t a;
    asm("{ .reg .u64 t; cvta.to.shared.u64 t, %1; cvt.u32.u64 %0, t; }" : "=r"(a) : "l"(p));
    return a;
}

#define CP_ASYNC16(s, g) \
    asm volatile("cp.async.cg.shared.global [%0], [%1], 16;" :: "r"(s), "l"(g) : "memory")
#define CP_COMMIT() asm volatile("cp.async.commit_group;" ::: "memory")
#define CP_WAIT1()  asm volatile("cp.async.wait_group 1;" ::: "memory")
#define CP_WAIT0()  asm volatile("cp.async.wait_group 0;" ::: "memory")

#define LDMATRIX_X4(r0, r1, r2, r3, addr) \
    asm volatile("ldmatrix.sync.aligned.m8n8.x4.shared.b16 {%0,%1,%2,%3}, [%4];" \
        : "=r"(r0), "=r"(r1), "=r"(r2), "=r"(r3) : "r"(addr))

#define MMA_16816(c0, c1, c2, c3, a0, a1, a2, a3, b0, b1) \
    asm volatile("mma.sync.aligned.m16n8k16.row.col.f32.bf16.bf16.f32 " \
        "{%0,%1,%2,%3}, {%4,%5,%6,%7}, {%8,%9}, {%0,%1,%2,%3};" \
        : "+f"(c0), "+f"(c1), "+f"(c2), "+f"(c3) \
        : "r"(a0), "r"(a1), "r"(a2), "r"(a3), "r"(b0), "r"(b1))

// ---------------- fast exp / log on the FMA pipe ---------------------------------
__device__ __forceinline__ float fast_exp(float x) {
    float t = x * 1.4426950408889634f;
    t = fmaxf(t, -127.0f);
    float n = rintf(t);
    float f = t - n;
    float p = 1.5403530393381609e-4f;
    p = fmaf(p, f, 1.3333558146428443e-3f);
    p = fmaf(p, f, 9.6181291076284772e-3f);
    p = fmaf(p, f, 5.5504108664821580e-2f);
    p = fmaf(p, f, 2.4022650695910072e-1f);
    p = fmaf(p, f, 6.9314718055994531e-1f);
    p = fmaf(p, f, 1.0f);
    return __int_as_float(((int)n + 127) << 23) * p;
}

__device__ __forceinline__ float fast_log(float x) {
    int i = __float_as_int(x);
    int e = ((i >> 23) & 255) - 127;
    float m = __int_as_float((i & 0x007fffff) | 0x3f800000);
    if (m > 1.4142135f) { m *= 0.5f; e++; }
    float u = m - 1.0f;
    float p = -0.125f;
    p = fmaf(p, u, 0.14285714285f);
    p = fmaf(p, u, -0.16666666667f);
    p = fmaf(p, u, 0.2f);
    p = fmaf(p, u, -0.25f);
    p = fmaf(p, u, 0.33333333333f);
    p = fmaf(p, u, -0.5f);
    p = fmaf(p, u, 1.0f);
    p *= u;
    return fmaf((float)e, 0.69314718056f, p);
}

// ---------------- K0: row norms ---------------------------------------------------
__global__ void __launch_bounds__(256) norm_kernel(const float* __restrict__ X) {
    int row = blockIdx.x * 8 + (threadIdx.x >> 5);
    int lane = threadIdx.x & 31;
    const float* xr = X + (size_t)row * D_DIM;
    float ss = 0.f;
    for (int i = lane; i < D_DIM; i += 32) { float v = xr[i]; ss = fmaf(v, v, ss); }
    #pragma unroll
    for (int o = 16; o > 0; o >>= 1) ss += __shfl_xor_sync(0xffffffffu, ss, o);
    if (lane == 0) g_inv_norm[row] = 1.0f / fmaxf(sqrtf(ss), 1e-7f);
}

// ---------------- split converters ------------------------------------------------
__global__ void __launch_bounds__(256) convA_kernel(const float* __restrict__ X) {
    size_t g = (size_t)blockIdx.x * 256 + threadIdx.x;   // pair index
    int row = (int)(g / (D_DIM / 2));
    int c2 = (int)(g % (D_DIM / 2)) * 2;
    float sc = g_inv_norm[row];
    float2 v = *(const float2*)(X + (size_t)row * D_DIM + c2);
    float a0 = v.x * sc, a1 = v.y * sc;
    __nv_bfloat16 h0 = __float2bfloat16(a0);
    __nv_bfloat16 h1 = __float2bfloat16(a1);
    __nv_bfloat16 m0 = __float2bfloat16(a0 - __bfloat162float(h0));
    __nv_bfloat16 m1 = __float2bfloat16(a1 - __bfloat162float(h1));
    __nv_bfloat16* rowp = g_A3 + (size_t)row * KTOT;
    *(__nv_bfloat162*)(rowp + c2)             = __nv_bfloat162(h0, h1);
    *(__nv_bfloat162*)(rowp + D_DIM + c2)     = __nv_bfloat162(h0, h1);
    *(__nv_bfloat162*)(rowp + 2 * D_DIM + c2) = __nv_bfloat162(m0, m1);
}

__global__ void __launch_bounds__(256) convB_kernel(const float* __restrict__ Wm) {
    size_t g = (size_t)blockIdx.x * 256 + threadIdx.x;
    int row = (int)(g / (D_DIM / 2));
    int c2 = (int)(g % (D_DIM / 2)) * 2;
    float2 v = *(const float2*)(Wm + (size_t)row * D_DIM + c2);
    __nv_bfloat16 h0 = __float2bfloat16(v.x);
    __nv_bfloat16 h1 = __float2bfloat16(v.y);
    __nv_bfloat16 m0 = __float2bfloat16(v.x - __bfloat162float(h0));
    __nv_bfloat16 m1 = __float2bfloat16(v.y - __bfloat162float(h1));
    __nv_bfloat16* rowp = g_B3 + (size_t)row * KTOT;
    *(__nv_bfloat162*)(rowp + c2)             = __nv_bfloat162(h0, h1);
    *(__nv_bfloat162*)(rowp + D_DIM + c2)     = __nv_bfloat162(m0, m1);
    *(__nv_bfloat162*)(rowp + 2 * D_DIM + c2) = __nv_bfloat162(h0, h1);
}

// ---------------- K1: HMMA GEMM (bf16x2 split, K=2304) + fused column stats ------
#define BM 128
#define BN 128
#define BKK 64
#define NIT (KTOT / BKK)            // 36
#define RSTR 144
#define STAGE_HALF (128 * RSTR)
#define STAGE_BYTES (2 * STAGE_HALF)
#define NSTAGE 3
#define GEMM_SMEM (NSTAGE * STAGE_BYTES)   // 110592 (2 CTA/SM)

__global__ void __launch_bounds__(256, 2) gemm_hmma(const __nv_bfloat16* __restrict__ A3,
                                                    const __nv_bfloat16* __restrict__ B3) {
    extern __shared__ char smem[];
    const uint32_t sbase = smem_u32(smem);
    const int tid = threadIdx.x;
    const int wid = tid >> 5, lid = tid & 31;
    const int bm = blockIdx.y * BM;
    const int bn = blockIdx.x * BN;
    const int wm = (wid & 1) * 64;
    const int wn = (wid >> 1) * 32;

    const __nv_bfloat16* gA[4];
    const __nv_bfloat16* gB[4];
    uint32_t so[4];
    #pragma unroll
    for (int i = 0; i < 4; i++) {
        const int ch = tid + i * 256;
        const int r = ch >> 3, c = ch & 7;
        gA[i] = A3 + (size_t)(bm + r) * KTOT + c * 8;
        gB[i] = B3 + (size_t)(bn + r) * KTOT + c * 8;
        so[i] = r * RSTR + c * 16;
    }

    const int lrow = (lid & 7) + ((lid >> 3) & 1) * 8;
    const int lkb = ((lid >> 4) & 1) * 16;
    const uint32_t aoff = (uint32_t)(wm + lrow) * RSTR + lkb;
    const uint32_t boff = (uint32_t)(wn + lrow) * RSTR + lkb;

    float acc[4][4][4];
    #pragma unroll
    for (int i = 0; i < 4; i++)
        #pragma unroll
        for (int j = 0; j < 4; j++)
            #pragma unroll
            for (int q = 0; q < 4; q++) acc[i][j][q] = 0.f;

    #pragma unroll
    for (int st = 0; st < 2; st++) {
        const int k0 = st * BKK;
        const uint32_t sa = sbase + st * STAGE_BYTES;
        const uint32_t sb = sa + STAGE_HALF;
        #pragma unroll
        for (int i = 0; i < 4; i++) {
            CP_ASYNC16(sa + so[i], gA[i] + k0);
            CP_ASYNC16(sb + so[i], gB[i] + k0);
        }
        CP_COMMIT();
    }

    int st = 0;
    for (int it = 0; it < NIT; it++) {
        CP_WAIT1();
        __syncthreads();

        if (it + 2 < NIT) {
            const int ps = (st + 2 >= NSTAGE) ? st + 2 - NSTAGE : st + 2;
            const int k0 = (it + 2) * BKK;
            const uint32_t sa = sbase + ps * STAGE_BYTES;
            const uint32_t sb = sa + STAGE_HALF;
            #pragma unroll
            for (int i = 0; i < 4; i++) {
                CP_ASYNC16(sa + so[i], gA[i] + k0);
                CP_ASYNC16(sb + so[i], gB[i] + k0);
            }
        }
        CP_COMMIT();

        const uint32_t sa = sbase + st * STAGE_BYTES;
        const uint32_t sb = sa + STAGE_HALF;
        #pragma unroll
        for (int ks = 0; ks < 4; ks++) {
            uint32_t a[4][4];
            #pragma unroll
            for (int mt = 0; mt < 4; mt++) {
                uint32_t ad = sa + aoff + mt * (16 * RSTR) + ks * 32;
                LDMATRIX_X4(a[mt][0], a[mt][1], a[mt][2], a[mt][3], ad);
            }
            uint32_t b[2][4];
            #pragma unroll
            for (int np = 0; np < 2; np++) {
                uint32_t bd = sb + boff + np * (16 * RSTR) + ks * 32;
                LDMATRIX_X4(b[np][0], b[np][1], b[np][2], b[np][3], bd);
            }
            #pragma unroll
            for (int mt = 0; mt < 4; mt++) {
                #pragma unroll
                for (int nt = 0; nt < 4; nt++) {
                    const int np = nt >> 1, no = nt & 1;
                    MMA_16816(acc[mt][nt][0], acc[mt][nt][1], acc[mt][nt][2], acc[mt][nt][3],
                              a[mt][0], a[mt][1], a[mt][2], a[mt][3],
                              b[np][no], b[np][2 + no]);
                }
            }
        }
        st = (st + 1 == NSTAGE) ? 0 : st + 1;
    }

    // ---- epilogue part 1: per-thread column stats ----
    float cm[8], cs[8];
    #pragma unroll
    for (int nt = 0; nt < 4; nt++) {
        #pragma unroll
        for (int o = 0; o < 2; o++) {
            float mx = -1e30f;
            #pragma unroll
            for (int mt = 0; mt < 4; mt++) {
                mx = fmaxf(mx, acc[mt][nt][o]);
                mx = fmaxf(mx, acc[mt][nt][2 + o]);
            }
            mx *= 20.0f;
            float sm = 0.f;
            #pragma unroll
            for (int mt = 0; mt < 4; mt++) {
                sm += fast_exp(fmaf(acc[mt][nt][o], 20.0f, -mx));
                sm += fast_exp(fmaf(acc[mt][nt][2 + o], 20.0f, -mx));
            }
            cm[nt * 2 + o] = mx;
            cs[nt * 2 + o] = sm;
        }
    }
    #pragma unroll
    for (int off = 4; off <= 16; off <<= 1) {
        #pragma unroll
        for (int i = 0; i < 8; i++) {
            float m2 = __shfl_xor_sync(0xffffffffu, cm[i], off);
            float s2 = __shfl_xor_sync(0xffffffffu, cs[i], off);
            float nm = fmaxf(cm[i], m2);
            cs[i] = cs[i] * fast_exp(cm[i] - nm) + s2 * fast_exp(m2 - nm);
            cm[i] = nm;
        }
    }

    // ---- epilogue part 2: store logits ----
    const int mrow = lid >> 2;
    const int mcol = (lid & 3) * 2;
    #pragma unroll
    for (int mt = 0; mt < 4; mt++) {
        #pragma unroll
        for (int nt = 0; nt < 4; nt++) {
            const int row = bm + wm + mt * 16 + mrow;
            const int col = bn + wn + nt * 8 + mcol;
            float2 v01 = make_float2(acc[mt][nt][0], acc[mt][nt][1]);
            float2 v23 = make_float2(acc[mt][nt][2], acc[mt][nt][3]);
            *(float2*)(g_logits + (size_t)row * K_DIM + col) = v01;
            *(float2*)(g_logits + (size_t)(row + 8) * K_DIM + col) = v23;
        }
    }

    // ---- epilogue part 3: combine the two m-warps, write per-CTA partial ----
    float* sbuf = (float*)smem;
    __syncthreads();
    if ((wid & 1) == 0 && lid < 4) {
        #pragma unroll
        for (int i = 0; i < 8; i++) {
            int c = (wid >> 1) * 32 + (i >> 1) * 8 + lid * 2 + (i & 1);
            sbuf[c * 2] = cm[i];
            sbuf[c * 2 + 1] = cs[i];
        }
    }
    __syncthreads();
    if ((wid & 1) == 1 && lid < 4) {
        const int mt32 = (bm & 4095) >> 7;
        const int sidx = bm >> 12;
        #pragma unroll
        for (int i = 0; i < 8; i++) {
            int c = (wid >> 1) * 32 + (i >> 1) * 8 + lid * 2 + (i & 1);
            float m2 = sbuf[c * 2], s2 = sbuf[c * 2 + 1];
            float nm = fmaxf(cm[i], m2);
            float ns = cs[i] * fast_exp(cm[i] - nm) + s2 * fast_exp(m2 - nm);
            int gidx = (mt32 * S_DIM + sidx) * K_DIM + bn + c;
            g_part_m[gidx] = nm;
            g_part_s[gidx] = ns;
        }
    }
}

// ---------------- K2: combine partials -> d, c=1; zero A -------------------------
__global__ void __launch_bounds__(256) combine1_kernel() {
    const int idx = blockIdx.x * 256 + threadIdx.x;     // s*K + k
    const int s = idx >> 13, k = idx & (K_DIM - 1);
    float m = -1e30f;
    #pragma unroll
    for (int i = 0; i < 32; i++)
        m = fmaxf(m, g_part_m[(i * S_DIM + s) * K_DIM + k]);
    float A = 0.f;
    #pragma unroll
    for (int i = 0; i < 32; i++) {
        const int pi = (i * S_DIM + s) * K_DIM + k;
        A = fmaf(g_part_s[pi], fast_exp(g_part_m[pi] - m), A);
    }
    float A1 = 5.1847055285870724e21f * A;   // * exp(50)
    g_c[idx] = 1.0f;
    g_d[idx] = m + logf(A1 + 1e-8f) - 50.0f;
    g_A[idx] = 0.f;
}

__global__ void __launch_bounds__(256) update_c_kernel() {
    const int idx = blockIdx.x * 256 + threadIdx.x;
    float c = g_c[idx], A = g_A[idx];
    g_c[idx] = c / (c * A + 1e-8f);
    g_A[idx] = 0.f;
    if (idx == 0) g_loss = 0.f;
}

// ---------------- row passes (cp.async double-buffered, t~ basis) -----------------
// Per row: wait prefetch -> bar -> issue next prefetch -> compute from smem buffer.
// MODE 1: buf = fp32 logits row (2x32KB); in-place overwrite with t~; write fp16 t~
// MODE 2: buf = fp16 t~ row (2x16KB); B2->r2, A3 partials
// MODE 3: buf = fp16 t~ row (2x16KB); B3->r3, output, fused loss
#define RP_SMEM1 (2 * 32768)
#define RP_SMEM23 (2 * 16384)

template <int MODE>
__global__ void __launch_bounds__(256) rowpass_kernel(float* __restrict__ outp) {
    extern __shared__ char dsm[];
    __shared__ float sA[8], sB[8];
    __shared__ float bcast[1];
    const uint32_t sb0 = smem_u32(dsm);
    const int ROWB = (MODE == 1) ? 32768 : 16384;   // bytes per row buffer
    const int tid = threadIdx.x;
    const int warp = tid >> 5, lane = tid & 31;
    const int r0 = blockIdx.x * RPC;
    const int s = r0 >> 12;
    const float4* __restrict__ cv = (const float4*)(g_c + s * K_DIM);
    const float4* __restrict__ dv = (const float4*)(g_d + s * K_DIM);

    float accR[32];
    if (MODE != 3) {
        #pragma unroll
        for (int j = 0; j < 32; j++) accR[j] = 0.f;
    }
    float lossAcc = 0.f;

    // prefetch helper: copy row 'row' into buffer b
    auto issue_row = [&](int row, int b) {
        const char* src = (MODE == 1)
            ? (const char*)(g_logits + (size_t)row * K_DIM)
            : (const char*)(g_that + (size_t)row * K_DIM);
        uint32_t dst = sb0 + b * ROWB;
        const int nch = ROWB / (256 * 16);   // 8 (f32) or 4 (f16)
        #pragma unroll
        for (int i = 0; i < 8; i++) {
            if (i < nch) {
                uint32_t off = (uint32_t)(tid + i * 256) * 16;
                CP_ASYNC16(dst + off, src + off);
            }
        }
        CP_COMMIT();
    };

    issue_row(r0, 0);

    for (int rr = 0; rr < RPC; rr++) {
        const int row = r0 + rr;
        const int cur = rr & 1;
        CP_WAIT0();
        __syncthreads();           // buffer cur ready for all; prior readers done
        if (rr + 1 < RPC) issue_row(row + 1, cur ^ 1);

        float4* bufF = (float4*)(dsm + cur * ROWB);
        uint2* bufH = (uint2*)(dsm + cur * ROWB);
        uint2* __restrict__ hwrow = (uint2*)(g_that + (size_t)row * K_DIM);

        float sumB = 0.f, sumV = 0.f, ls = 0.f;
        #pragma unroll
        for (int j = 0; j < 8; j++) {
            const int k4 = tid + (j << 8);
            if (MODE == 1) {
                float4 l4 = bufF[k4];
                float4 d4 = dv[k4];
                float t0 = fast_exp(fmaf(l4.x, 20.0f, -d4.x));
                float t1 = fast_exp(fmaf(l4.y, 20.0f, -d4.y));
                float t2 = fast_exp(fmaf(l4.z, 20.0f, -d4.z));
                float t3 = fast_exp(fmaf(l4.w, 20.0f, -d4.w));
                sumB += (t0 + t1) + (t2 + t3);
                bufF[k4] = make_float4(t0, t1, t2, t3);   // in-place: t~ for phase 2
                __half2 h01 = __floats2half2_rn(t0, t1);
                __half2 h23 = __floats2half2_rn(t2, t3);
                hwrow[k4] = make_uint2(*(uint32_t*)&h01, *(uint32_t*)&h23);
                float e0 = fast_exp(l4.x * 8.3333333333333339f);
                float e1 = fast_exp(l4.y * 8.3333333333333339f);
                float e2 = fast_exp(l4.z * 8.3333333333333339f);
                float e3 = fast_exp(l4.w * 8.3333333333333339f);
                ls += (e0 + e1) + (e2 + e3);
            } else if (MODE == 2) {
                uint2 u = bufH[k4];
                float2 f01 = __half22float2(*(__half2*)&u.x);
                float2 f23 = __half22float2(*(__half2*)&u.y);
                float4 c4 = cv[k4];
                sumB = fmaf(f01.x, c4.x, sumB);
                sumB = fmaf(f01.y, c4.y, sumB);
                sumB = fmaf(f23.x, c4.z, sumB);
                sumB = fmaf(f23.y, c4.w, sumB);
            } else {
                uint2 u = bufH[k4];
                float2 f01 = __half22float2(*(__half2*)&u.x);
                float2 f23 = __half22float2(*(__half2*)&u.y);
                float4 c4 = cv[k4];
                float4 d4 = dv[k4];
                float th[4] = {f01.x, f01.y, f23.x, f23.y};
                float cc[4] = {c4.x, c4.y, c4.z, c4.w};
                float dd[4] = {d4.x, d4.y, d4.z, d4.w};
                #pragma unroll
                for (int q = 0; q < 4; q++) {
                    float t = th[q] * cc[q];
                    sumB += t;
                    float pred = (fast_log(fmaxf(th[q], 6e-8f)) + dd[q]) * 0.41666666666666669f;
                    sumV = fmaf(t, pred, sumV);
                }
            }
        }
        #pragma unroll
        for (int o = 16; o > 0; o >>= 1) {
            sumB += __shfl_xor_sync(0xffffffffu, sumB, o);
            if (MODE == 3) sumV += __shfl_xor_sync(0xffffffffu, sumV, o);
            if (MODE == 1) ls += __shfl_xor_sync(0xffffffffu, ls, o);
        }
        if (lane == 0) {
            sA[warp] = sumB;
            if (MODE == 3) sB[warp] = sumV;
            if (MODE == 1) sB[warp] = ls;
        }
        __syncthreads();
        if (tid == 0) {
            float Bt = 0.f, Vt = 0.f, Lt = 0.f;
            #pragma unroll
            for (int w = 0; w < 8; w++) {
                Bt += sA[w];
                if (MODE == 3) Vt += sB[w];
                if (MODE == 1) Lt += sB[w];
            }
            float rnew;
            if (MODE == 1) {
                rnew = 1.0f / (Bt + 1e-8f);
                g_r[row] = rnew;
                g_lse[row] = logf(Lt);
            } else {
                float rold = g_r[row];
                rnew = rold / (rold * Bt + 1e-8f);
                if (MODE == 2) g_r[row] = rnew;
                if (MODE == 3) lossAcc = fmaf(rnew, g_lse[row] * Bt - Vt, lossAcc);
            }
            bcast[0] = rnew;
        }
        __syncthreads();
        const float rnew = bcast[0];
        if (MODE == 3) {
            float4* orow = (float4*)(outp + (size_t)row * K_DIM);
            #pragma unroll
            for (int j = 0; j < 8; j++) {
                const int k4 = tid + (j << 8);
                uint2 u = bufH[k4];
                float2 f01 = __half22float2(*(__half2*)&u.x);
                float2 f23 = __half22float2(*(__half2*)&u.y);
                float4 c4 = cv[k4];
                orow[k4] = make_float4(f01.x * c4.x * rnew, f01.y * c4.y * rnew,
                                       f23.x * c4.z * rnew, f23.y * c4.w * rnew);
            }
        } else if (MODE == 2) {
            #pragma unroll
            for (int j = 0; j < 8; j++) {
                const int k4 = tid + (j << 8);
                uint2 u = bufH[k4];
                float2 f01 = __half22float2(*(__half2*)&u.x);
                float2 f23 = __half22float2(*(__half2*)&u.y);
                accR[j * 4 + 0] = fmaf(f01.x, rnew, accR[j * 4 + 0]);
                accR[j * 4 + 1] = fmaf(f01.y, rnew, accR[j * 4 + 1]);
                accR[j * 4 + 2] = fmaf(f23.x, rnew, accR[j * 4 + 2]);
                accR[j * 4 + 3] = fmaf(f23.y, rnew, accR[j * 4 + 3]);
            }
        } else {
            #pragma unroll
            for (int j = 0; j < 8; j++) {
                const int k4 = tid + (j << 8);
                float4 v = bufF[k4];
                accR[j * 4 + 0] = fmaf(v.x, rnew, accR[j * 4 + 0]);
                accR[j * 4 + 1] = fmaf(v.y, rnew, accR[j * 4 + 1]);
                accR[j * 4 + 2] = fmaf(v.z, rnew, accR[j * 4 + 2]);
                accR[j * 4 + 3] = fmaf(v.w, rnew, accR[j * 4 + 3]);
            }
        }
    }

    if (MODE != 3) {
        float* Ag = g_A + s * K_DIM;
        #pragma unroll
        for (int j = 0; j < 8; j++) {
            const int kb = 4 * (tid + (j << 8));
            atomicAdd(&Ag[kb + 0], accR[j * 4 + 0]);
            atomicAdd(&Ag[kb + 1], accR[j * 4 + 1]);
            atomicAdd(&Ag[kb + 2], accR[j * 4 + 2]);
            atomicAdd(&Ag[kb + 3], accR[j * 4 + 3]);
        }
    } else {
        if (tid == 0) atomicAdd(&g_loss, lossAcc);
    }
}

__global__ void finalize_kernel(float* dst) {
    dst[0] = g_loss * (1.0f / 16384.0f);
}

// ---------------- launch ----------------------------------------------------------
extern "C" void kernel_launch(void* const* d_in, const int* in_sizes, int n_in,
                              void* d_out, int out_size) {
    const float* x = (const float*)d_in[0];
    const float* W = (const float*)d_in[1];
    if (n_in >= 2 && in_sizes[0] == K_DIM * D_DIM && in_sizes[1] == N_ROWS * D_DIM) {
        const float* t = x; x = W; W = t;
    }
    float* out = (float*)d_out;

    float* outp = out;
    if ((long long)out_size < TOT_ELEMS) {
        void* p = nullptr;
        cudaGetSymbolAddress(&p, g_logits);
        outp = (float*)p;
    }

    void *pA3, *pB3;
    cudaGetSymbolAddress(&pA3, g_A3);
    cudaGetSymbolAddress(&pB3, g_B3);

    cudaFuncSetAttribute(gemm_hmma, cudaFuncAttributeMaxDynamicSharedMemorySize, GEMM_SMEM);
    cudaFuncSetAttribute(rowpass_kernel<1>, cudaFuncAttributeMaxDynamicSharedMemorySize, RP_SMEM1);
    cudaFuncSetAttribute(rowpass_kernel<2>, cudaFuncAttributeMaxDynamicSharedMemorySize, RP_SMEM23);
    cudaFuncSetAttribute(rowpass_kernel<3>, cudaFuncAttributeMaxDynamicSharedMemorySize, RP_SMEM23);

    norm_kernel<<<N_ROWS / 8, 256>>>(x);
    convA_kernel<<<(N_ROWS * (D_DIM / 2)) / 256, 256>>>(x);
    convB_kernel<<<(K_DIM * (D_DIM / 2)) / 256, 256>>>(W);

    gemm_hmma<<<dim3(K_DIM / BN, N_ROWS / BM), 256, GEMM_SMEM>>>(
        (const __nv_bfloat16*)pA3, (const __nv_bfloat16*)pB3);

    combine1_kernel<<<(S_DIM * K_DIM) / 256, 256>>>();

    rowpass_kernel<1><<<N_ROWS / RPC, 256, RP_SMEM1>>>(nullptr);
    update_c_kernel<<<(S_DIM * K_DIM) / 256, 256>>>();
    rowpass_kernel<2><<<N_ROWS / RPC, 256, RP_SMEM23>>>(nullptr);
    update_c_kernel<<<(S_DIM * K_DIM) / 256, 256>>>();
    rowpass_kernel<3><<<N_ROWS / RPC, 256, RP_SMEM23>>>(outp);

    if ((long long)out_size > TOT_ELEMS) {
        finalize_kernel<<<1, 1>>>(out + TOT_ELEMS);
    } else if (out_size == 1) {
        finalize_kernel<<<1, 1>>>(out);
    }
}

// round 16
// speedup vs baseline: 1.5213x; 1.5213x over previous
#include <cuda_runtime.h>
#include <cuda_bf16.h>
#include <cuda_fp16.h>
#include <math.h>
#include <stdint.h>

#define S_DIM 4
#define B_DIM 4096
#define D_DIM 768
#define K_DIM 8192
#define N_ROWS 16384
#define RPC 16                  // rows per CTA in row passes
#define TOT_ELEMS 134217728LL   // N_ROWS * K_DIM

#define KTOT 2304               // 3 * D_DIM (concatenated split planes)

// ---------------- scratch (device globals; no allocation allowed) ----------------
__device__ float g_logits[(size_t)N_ROWS * K_DIM];   // 512 MB
__device__ __half g_that[(size_t)N_ROWS * K_DIM];    // 256 MB   t~ (fp16)
__device__ float g_inv_norm[N_ROWS];
__device__ float g_c[S_DIM * K_DIM];                 // c-hat (t~ basis), init 1
__device__ float g_d[S_DIM * K_DIM];                 // shift + ln(A1+eps) - 50
__device__ float g_A[S_DIM * K_DIM];
__device__ float g_r[N_ROWS];
__device__ float g_lse[N_ROWS];
// per-mtile column partials written by the GEMM epilogue: [32 mtiles][S][K]
__device__ float g_part_m[32 * S_DIM * K_DIM];
__device__ float g_part_s[32 * S_DIM * K_DIM];
__device__ float g_loss;

// concatenated bf16 split planes:  A3 = [Ah | Ah | Am],  B3 = [Bh | Bm | Bh]
__device__ __nv_bfloat16 g_A3[(size_t)N_ROWS * KTOT];   // 75.5 MB
__device__ __nv_bfloat16 g_B3[(size_t)K_DIM * KTOT];    // 37.7 MB

// ---------------- helpers ---------------------------------------------------------
__device__ __forceinline__ uint32_t smem_u32(const void* p) {
    uint32_t a;
    asm("{ .reg .u64 t; cvta.to.shared.u64 t, %1; cvt.u32.u64 %0, t; }" : "=r"(a) : "l"(p));
    return a;
}

#define CP_ASYNC16(s, g) \
    asm volatile("cp.async.cg.shared.global [%0], [%1], 16;" :: "r"(s), "l"(g) : "memory")
#define CP_COMMIT() asm volatile("cp.async.commit_group;" ::: "memory")
#define CP_WAIT1()  asm volatile("cp.async.wait_group 1;" ::: "memory")

#define LDMATRIX_X4(r0, r1, r2, r3, addr) \
    asm volatile("ldmatrix.sync.aligned.m8n8.x4.shared.b16 {%0,%1,%2,%3}, [%4];" \
        : "=r"(r0), "=r"(r1), "=r"(r2), "=r"(r3) : "r"(addr))

#define MMA_16816(c0, c1, c2, c3, a0, a1, a2, a3, b0, b1) \
    asm volatile("mma.sync.aligned.m16n8k16.row.col.f32.bf16.bf16.f32 " \
        "{%0,%1,%2,%3}, {%4,%5,%6,%7}, {%8,%9}, {%0,%1,%2,%3};" \
        : "+f"(c0), "+f"(c1), "+f"(c2), "+f"(c3) \
        : "r"(a0), "r"(a1), "r"(a2), "r"(a3), "r"(b0), "r"(b1))

// ---------------- fast exp / log on the FMA pipe ---------------------------------
__device__ __forceinline__ float fast_exp(float x) {
    float t = x * 1.4426950408889634f;
    t = fmaxf(t, -127.0f);
    float n = rintf(t);
    float f = t - n;
    float p = 1.5403530393381609e-4f;
    p = fmaf(p, f, 1.3333558146428443e-3f);
    p = fmaf(p, f, 9.6181291076284772e-3f);
    p = fmaf(p, f, 5.5504108664821580e-2f);
    p = fmaf(p, f, 2.4022650695910072e-1f);
    p = fmaf(p, f, 6.9314718055994531e-1f);
    p = fmaf(p, f, 1.0f);
    return __int_as_float(((int)n + 127) << 23) * p;
}

__device__ __forceinline__ float fast_log(float x) {
    int i = __float_as_int(x);
    int e = ((i >> 23) & 255) - 127;
    float m = __int_as_float((i & 0x007fffff) | 0x3f800000);
    if (m > 1.4142135f) { m *= 0.5f; e++; }
    float u = m - 1.0f;
    float p = -0.125f;
    p = fmaf(p, u, 0.14285714285f);
    p = fmaf(p, u, -0.16666666667f);
    p = fmaf(p, u, 0.2f);
    p = fmaf(p, u, -0.25f);
    p = fmaf(p, u, 0.33333333333f);
    p = fmaf(p, u, -0.5f);
    p = fmaf(p, u, 1.0f);
    p *= u;
    return fmaf((float)e, 0.69314718056f, p);
}

// ---------------- K0: row norms ---------------------------------------------------
__global__ void __launch_bounds__(256) norm_kernel(const float* __restrict__ X) {
    int row = blockIdx.x * 8 + (threadIdx.x >> 5);
    int lane = threadIdx.x & 31;
    const float* xr = X + (size_t)row * D_DIM;
    float ss = 0.f;
    for (int i = lane; i < D_DIM; i += 32) { float v = xr[i]; ss = fmaf(v, v, ss); }
    #pragma unroll
    for (int o = 16; o > 0; o >>= 1) ss += __shfl_xor_sync(0xffffffffu, ss, o);
    if (lane == 0) g_inv_norm[row] = 1.0f / fmaxf(sqrtf(ss), 1e-7f);
}

// ---------------- split converters ------------------------------------------------
__global__ void __launch_bounds__(256) convA_kernel(const float* __restrict__ X) {
    size_t g = (size_t)blockIdx.x * 256 + threadIdx.x;   // pair index
    int row = (int)(g / (D_DIM / 2));
    int c2 = (int)(g % (D_DIM / 2)) * 2;
    float sc = g_inv_norm[row];
    float2 v = *(const float2*)(X + (size_t)row * D_DIM + c2);
    float a0 = v.x * sc, a1 = v.y * sc;
    __nv_bfloat16 h0 = __float2bfloat16(a0);
    __nv_bfloat16 h1 = __float2bfloat16(a1);
    __nv_bfloat16 m0 = __float2bfloat16(a0 - __bfloat162float(h0));
    __nv_bfloat16 m1 = __float2bfloat16(a1 - __bfloat162float(h1));
    __nv_bfloat16* rowp = g_A3 + (size_t)row * KTOT;
    *(__nv_bfloat162*)(rowp + c2)             = __nv_bfloat162(h0, h1);
    *(__nv_bfloat162*)(rowp + D_DIM + c2)     = __nv_bfloat162(h0, h1);
    *(__nv_bfloat162*)(rowp + 2 * D_DIM + c2) = __nv_bfloat162(m0, m1);
}

__global__ void __launch_bounds__(256) convB_kernel(const float* __restrict__ Wm) {
    size_t g = (size_t)blockIdx.x * 256 + threadIdx.x;
    int row = (int)(g / (D_DIM / 2));
    int c2 = (int)(g % (D_DIM / 2)) * 2;
    float2 v = *(const float2*)(Wm + (size_t)row * D_DIM + c2);
    __nv_bfloat16 h0 = __float2bfloat16(v.x);
    __nv_bfloat16 h1 = __float2bfloat16(v.y);
    __nv_bfloat16 m0 = __float2bfloat16(v.x - __bfloat162float(h0));
    __nv_bfloat16 m1 = __float2bfloat16(v.y - __bfloat162float(h1));
    __nv_bfloat16* rowp = g_B3 + (size_t)row * KTOT;
    *(__nv_bfloat162*)(rowp + c2)             = __nv_bfloat162(h0, h1);
    *(__nv_bfloat162*)(rowp + D_DIM + c2)     = __nv_bfloat162(m0, m1);
    *(__nv_bfloat162*)(rowp + 2 * D_DIM + c2) = __nv_bfloat162(h0, h1);
}

// ---------------- K1: HMMA GEMM (bf16x2 split, K=2304) + fused column stats ------
#define BM 128
#define BN 128
#define BKK 64
#define NIT (KTOT / BKK)            // 36
#define RSTR 144
#define STAGE_HALF (128 * RSTR)
#define STAGE_BYTES (2 * STAGE_HALF)
#define NSTAGE 3
#define GEMM_SMEM (NSTAGE * STAGE_BYTES)   // 110592 (2 CTA/SM)

__global__ void __launch_bounds__(256, 2) gemm_hmma(const __nv_bfloat16* __restrict__ A3,
                                                    const __nv_bfloat16* __restrict__ B3) {
    extern __shared__ char smem[];
    const uint32_t sbase = smem_u32(smem);
    const int tid = threadIdx.x;
    const int wid = tid >> 5, lid = tid & 31;
    const int bm = blockIdx.y * BM;
    const int bn = blockIdx.x * BN;
    const int wm = (wid & 1) * 64;
    const int wn = (wid >> 1) * 32;

    const __nv_bfloat16* gA[4];
    const __nv_bfloat16* gB[4];
    uint32_t so[4];
    #pragma unroll
    for (int i = 0; i < 4; i++) {
        const int ch = tid + i * 256;
        const int r = ch >> 3, c = ch & 7;
        gA[i] = A3 + (size_t)(bm + r) * KTOT + c * 8;
        gB[i] = B3 + (size_t)(bn + r) * KTOT + c * 8;
        so[i] = r * RSTR + c * 16;
    }

    const int lrow = (lid & 7) + ((lid >> 3) & 1) * 8;
    const int lkb = ((lid >> 4) & 1) * 16;
    const uint32_t aoff = (uint32_t)(wm + lrow) * RSTR + lkb;
    const uint32_t boff = (uint32_t)(wn + lrow) * RSTR + lkb;

    float acc[4][4][4];
    #pragma unroll
    for (int i = 0; i < 4; i++)
        #pragma unroll
        for (int j = 0; j < 4; j++)
            #pragma unroll
            for (int q = 0; q < 4; q++) acc[i][j][q] = 0.f;

    #pragma unroll
    for (int st = 0; st < 2; st++) {
        const int k0 = st * BKK;
        const uint32_t sa = sbase + st * STAGE_BYTES;
        const uint32_t sb = sa + STAGE_HALF;
        #pragma unroll
        for (int i = 0; i < 4; i++) {
            CP_ASYNC16(sa + so[i], gA[i] + k0);
            CP_ASYNC16(sb + so[i], gB[i] + k0);
        }
        CP_COMMIT();
    }

    int st = 0;
    for (int it = 0; it < NIT; it++) {
        CP_WAIT1();
        __syncthreads();

        if (it + 2 < NIT) {
            const int ps = (st + 2 >= NSTAGE) ? st + 2 - NSTAGE : st + 2;
            const int k0 = (it + 2) * BKK;
            const uint32_t sa = sbase + ps * STAGE_BYTES;
            const uint32_t sb = sa + STAGE_HALF;
            #pragma unroll
            for (int i = 0; i < 4; i++) {
                CP_ASYNC16(sa + so[i], gA[i] + k0);
                CP_ASYNC16(sb + so[i], gB[i] + k0);
            }
        }
        CP_COMMIT();

        const uint32_t sa = sbase + st * STAGE_BYTES;
        const uint32_t sb = sa + STAGE_HALF;
        #pragma unroll
        for (int ks = 0; ks < 4; ks++) {
            uint32_t a[4][4];
            #pragma unroll
            for (int mt = 0; mt < 4; mt++) {
                uint32_t ad = sa + aoff + mt * (16 * RSTR) + ks * 32;
                LDMATRIX_X4(a[mt][0], a[mt][1], a[mt][2], a[mt][3], ad);
            }
            uint32_t b[2][4];
            #pragma unroll
            for (int np = 0; np < 2; np++) {
                uint32_t bd = sb + boff + np * (16 * RSTR) + ks * 32;
                LDMATRIX_X4(b[np][0], b[np][1], b[np][2], b[np][3], bd);
            }
            #pragma unroll
            for (int mt = 0; mt < 4; mt++) {
                #pragma unroll
                for (int nt = 0; nt < 4; nt++) {
                    const int np = nt >> 1, no = nt & 1;
                    MMA_16816(acc[mt][nt][0], acc[mt][nt][1], acc[mt][nt][2], acc[mt][nt][3],
                              a[mt][0], a[mt][1], a[mt][2], a[mt][3],
                              b[np][no], b[np][2 + no]);
                }
            }
        }
        st = (st + 1 == NSTAGE) ? 0 : st + 1;
    }

    // ---- epilogue part 1: per-thread column stats ----
    float cm[8], cs[8];
    #pragma unroll
    for (int nt = 0; nt < 4; nt++) {
        #pragma unroll
        for (int o = 0; o < 2; o++) {
            float mx = -1e30f;
            #pragma unroll
            for (int mt = 0; mt < 4; mt++) {
                mx = fmaxf(mx, acc[mt][nt][o]);
                mx = fmaxf(mx, acc[mt][nt][2 + o]);
            }
            mx *= 20.0f;
            float sm = 0.f;
            #pragma unroll
            for (int mt = 0; mt < 4; mt++) {
                sm += fast_exp(fmaf(acc[mt][nt][o], 20.0f, -mx));
                sm += fast_exp(fmaf(acc[mt][nt][2 + o], 20.0f, -mx));
            }
            cm[nt * 2 + o] = mx;
            cs[nt * 2 + o] = sm;
        }
    }
    #pragma unroll
    for (int off = 4; off <= 16; off <<= 1) {
        #pragma unroll
        for (int i = 0; i < 8; i++) {
            float m2 = __shfl_xor_sync(0xffffffffu, cm[i], off);
            float s2 = __shfl_xor_sync(0xffffffffu, cs[i], off);
            float nm = fmaxf(cm[i], m2);
            cs[i] = cs[i] * fast_exp(cm[i] - nm) + s2 * fast_exp(m2 - nm);
            cm[i] = nm;
        }
    }

    // ---- epilogue part 2: store logits ----
    const int mrow = lid >> 2;
    const int mcol = (lid & 3) * 2;
    #pragma unroll
    for (int mt = 0; mt < 4; mt++) {
        #pragma unroll
        for (int nt = 0; nt < 4; nt++) {
            const int row = bm + wm + mt * 16 + mrow;
            const int col = bn + wn + nt * 8 + mcol;
            float2 v01 = make_float2(acc[mt][nt][0], acc[mt][nt][1]);
            float2 v23 = make_float2(acc[mt][nt][2], acc[mt][nt][3]);
            *(float2*)(g_logits + (size_t)row * K_DIM + col) = v01;
            *(float2*)(g_logits + (size_t)(row + 8) * K_DIM + col) = v23;
        }
    }

    // ---- epilogue part 3: combine the two m-warps, write per-CTA partial ----
    float* sbuf = (float*)smem;
    __syncthreads();
    if ((wid & 1) == 0 && lid < 4) {
        #pragma unroll
        for (int i = 0; i < 8; i++) {
            int c = (wid >> 1) * 32 + (i >> 1) * 8 + lid * 2 + (i & 1);
            sbuf[c * 2] = cm[i];
            sbuf[c * 2 + 1] = cs[i];
        }
    }
    __syncthreads();
    if ((wid & 1) == 1 && lid < 4) {
        const int mt32 = (bm & 4095) >> 7;
        const int sidx = bm >> 12;
        #pragma unroll
        for (int i = 0; i < 8; i++) {
            int c = (wid >> 1) * 32 + (i >> 1) * 8 + lid * 2 + (i & 1);
            float m2 = sbuf[c * 2], s2 = sbuf[c * 2 + 1];
            float nm = fmaxf(cm[i], m2);
            float ns = cs[i] * fast_exp(cm[i] - nm) + s2 * fast_exp(m2 - nm);
            int gidx = (mt32 * S_DIM + sidx) * K_DIM + bn + c;
            g_part_m[gidx] = nm;
            g_part_s[gidx] = ns;
        }
    }
}

// ---------------- K2: combine partials -> d, c=1; zero A -------------------------
__global__ void __launch_bounds__(256) combine1_kernel() {
    const int idx = blockIdx.x * 256 + threadIdx.x;     // s*K + k
    const int s = idx >> 13, k = idx & (K_DIM - 1);
    float m = -1e30f;
    #pragma unroll
    for (int i = 0; i < 32; i++)
        m = fmaxf(m, g_part_m[(i * S_DIM + s) * K_DIM + k]);
    float A = 0.f;
    #pragma unroll
    for (int i = 0; i < 32; i++) {
        const int pi = (i * S_DIM + s) * K_DIM + k;
        A = fmaf(g_part_s[pi], fast_exp(g_part_m[pi] - m), A);
    }
    float A1 = 5.1847055285870724e21f * A;   // * exp(50)
    g_c[idx] = 1.0f;
    g_d[idx] = m + logf(A1 + 1e-8f) - 50.0f;
    g_A[idx] = 0.f;
}

__global__ void __launch_bounds__(256) update_c_kernel() {
    const int idx = blockIdx.x * 256 + threadIdx.x;
    float c = g_c[idx], A = g_A[idx];
    g_c[idx] = c / (c * A + 1e-8f);
    g_A[idx] = 0.f;
    if (idx == 0) g_loss = 0.f;
}

// ---------------- row passes (float4-vectorized, t~ basis) ------------------------
// element mapping: k = 4*(tid + j*256) + q,  j = 0..7, q = 0..3
// MODE 1: read logits f32x4; t~=exp(20l-d) -> g_that; B1->r1; branch-free LSE
// MODE 2: read t~ x4; B2 -> r2, A3 partials   (no exp)
// MODE 3: read t~ x4; B3 -> r3, output f32x4, fused loss via fast_log
template <int MODE>
__global__ void __launch_bounds__(256) rowpass_kernel(float* __restrict__ outp) {
    __shared__ float4 seb4[8 * 256];   // 32 KB staging
    __shared__ float sA[8], sB[8], sC[8];
    __shared__ float bcast[1];
    const int tid = threadIdx.x;
    const int warp = tid >> 5, lane = tid & 31;
    const int r0 = blockIdx.x * RPC;
    const int s = r0 >> 12;
    const float4* __restrict__ cv = (const float4*)(g_c + s * K_DIM);
    const float4* __restrict__ dv = (const float4*)(g_d + s * K_DIM);

    float accR[32];
    if (MODE != 3) {
        #pragma unroll
        for (int j = 0; j < 32; j++) accR[j] = 0.f;
    }
    float lossAcc = 0.f;

    for (int rr = 0; rr < RPC; rr++) {
        const int row = r0 + rr;
        const float4* __restrict__ lrow = (const float4*)(g_logits + (size_t)row * K_DIM);
        const uint2* __restrict__ hrow = (const uint2*)(g_that + (size_t)row * K_DIM);
        uint2* __restrict__ hwrow = (uint2*)(g_that + (size_t)row * K_DIM);
        float sumB = 0.f, sumV = 0.f;
        float ls = 0.f;
        #pragma unroll
        for (int j = 0; j < 8; j++) {
            const int k4 = tid + (j << 8);
            if (MODE == 1) {
                float4 l4 = lrow[k4];
                float4 d4 = dv[k4];
                float t0 = fast_exp(fmaf(l4.x, 20.0f, -d4.x));
                float t1 = fast_exp(fmaf(l4.y, 20.0f, -d4.y));
                float t2 = fast_exp(fmaf(l4.z, 20.0f, -d4.z));
                float t3 = fast_exp(fmaf(l4.w, 20.0f, -d4.w));
                sumB += (t0 + t1) + (t2 + t3);
                seb4[k4] = make_float4(t0, t1, t2, t3);
                __half2 h01 = __floats2half2_rn(t0, t1);
                __half2 h23 = __floats2half2_rn(t2, t3);
                hwrow[k4] = make_uint2(*(uint32_t*)&h01, *(uint32_t*)&h23);
                // branch-free LSE: pred = l/0.12 <= ~47 -> exp fits fp32
                float e0 = fast_exp(l4.x * 8.3333333333333339f);
                float e1 = fast_exp(l4.y * 8.3333333333333339f);
                float e2 = fast_exp(l4.z * 8.3333333333333339f);
                float e3 = fast_exp(l4.w * 8.3333333333333339f);
                ls += (e0 + e1) + (e2 + e3);
            } else if (MODE == 2) {
                uint2 u = hrow[k4];
                float2 f01 = __half22float2(*(__half2*)&u.x);
                float2 f23 = __half22float2(*(__half2*)&u.y);
                float4 c4 = cv[k4];
                sumB = fmaf(f01.x, c4.x, sumB);
                sumB = fmaf(f01.y, c4.y, sumB);
                sumB = fmaf(f23.x, c4.z, sumB);
                sumB = fmaf(f23.y, c4.w, sumB);
                seb4[k4] = make_float4(f01.x, f01.y, f23.x, f23.y);
            } else {
                uint2 u = hrow[k4];
                float2 f01 = __half22float2(*(__half2*)&u.x);
                float2 f23 = __half22float2(*(__half2*)&u.y);
                float4 c4 = cv[k4];
                float4 d4 = dv[k4];
                float th[4] = {f01.x, f01.y, f23.x, f23.y};
                float cc[4] = {c4.x, c4.y, c4.z, c4.w};
                float dd[4] = {d4.x, d4.y, d4.z, d4.w};
                float t[4];
                #pragma unroll
                for (int q = 0; q < 4; q++) {
                    t[q] = th[q] * cc[q];
                    sumB += t[q];
                    float pred = (fast_log(fmaxf(th[q], 6e-8f)) + dd[q]) * 0.41666666666666669f;
                    sumV = fmaf(t[q], pred, sumV);
                }
                seb4[k4] = make_float4(t[0], t[1], t[2], t[3]);
            }
        }
        #pragma unroll
        for (int o = 16; o > 0; o >>= 1) {
            sumB += __shfl_xor_sync(0xffffffffu, sumB, o);
            if (MODE == 3) sumV += __shfl_xor_sync(0xffffffffu, sumV, o);
            if (MODE == 1) ls += __shfl_xor_sync(0xffffffffu, ls, o);
        }
        if (lane == 0) {
            sA[warp] = sumB;
            if (MODE == 3) sB[warp] = sumV;
            if (MODE == 1) sB[warp] = ls;
        }
        __syncthreads();
        if (tid == 0) {
            float Bt = 0.f, Vt = 0.f, Lt = 0.f;
            #pragma unroll
            for (int w = 0; w < 8; w++) {
                Bt += sA[w];
                if (MODE == 3) Vt += sB[w];
                if (MODE == 1) Lt += sB[w];
            }
            float rnew;
            if (MODE == 1) {
                rnew = 1.0f / (Bt + 1e-8f);
                g_r[row] = rnew;
                g_lse[row] = logf(Lt);
            } else {
                float rold = g_r[row];
                rnew = rold / (rold * Bt + 1e-8f);
                if (MODE == 2) g_r[row] = rnew;
                if (MODE == 3) lossAcc = fmaf(rnew, g_lse[row] * Bt - Vt, lossAcc);
            }
            bcast[0] = rnew;
        }
        __syncthreads();
        const float rnew = bcast[0];
        if (MODE == 3) {
            float4* orow = (float4*)(outp + (size_t)row * K_DIM);
            #pragma unroll
            for (int j = 0; j < 8; j++) {
                const int k4 = tid + (j << 8);
                float4 v = seb4[k4];
                orow[k4] = make_float4(v.x * rnew, v.y * rnew, v.z * rnew, v.w * rnew);
            }
        } else {
            #pragma unroll
            for (int j = 0; j < 8; j++) {
                const int k4 = tid + (j << 8);
                float4 v = seb4[k4];
                accR[j * 4 + 0] = fmaf(v.x, rnew, accR[j * 4 + 0]);
                accR[j * 4 + 1] = fmaf(v.y, rnew, accR[j * 4 + 1]);
                accR[j * 4 + 2] = fmaf(v.z, rnew, accR[j * 4 + 2]);
                accR[j * 4 + 3] = fmaf(v.w, rnew, accR[j * 4 + 3]);
            }
        }
        __syncthreads();
    }

    if (MODE != 3) {
        float* Ag = g_A + s * K_DIM;
        #pragma unroll
        for (int j = 0; j < 8; j++) {
            const int kb = 4 * (tid + (j << 8));
            atomicAdd(&Ag[kb + 0], accR[j * 4 + 0]);
            atomicAdd(&Ag[kb + 1], accR[j * 4 + 1]);
            atomicAdd(&Ag[kb + 2], accR[j * 4 + 2]);
            atomicAdd(&Ag[kb + 3], accR[j * 4 + 3]);
        }
    } else {
        if (tid == 0) atomicAdd(&g_loss, lossAcc);
    }
}

__global__ void finalize_kernel(float* dst) {
    dst[0] = g_loss * (1.0f / 16384.0f);
}

// ---------------- launch ----------------------------------------------------------
extern "C" void kernel_launch(void* const* d_in, const int* in_sizes, int n_in,
                              void* d_out, int out_size) {
    const float* x = (const float*)d_in[0];
    const float* W = (const float*)d_in[1];
    if (n_in >= 2 && in_sizes[0] == K_DIM * D_DIM && in_sizes[1] == N_ROWS * D_DIM) {
        const float* t = x; x = W; W = t;
    }
    float* out = (float*)d_out;

    float* outp = out;
    if ((long long)out_size < TOT_ELEMS) {
        void* p = nullptr;
        cudaGetSymbolAddress(&p, g_logits);
        outp = (float*)p;
    }

    void *pA3, *pB3;
    cudaGetSymbolAddress(&pA3, g_A3);
    cudaGetSymbolAddress(&pB3, g_B3);

    cudaFuncSetAttribute(gemm_hmma, cudaFuncAttributeMaxDynamicSharedMemorySize, GEMM_SMEM);

    norm_kernel<<<N_ROWS / 8, 256>>>(x);
    convA_kernel<<<(N_ROWS * (D_DIM / 2)) / 256, 256>>>(x);
    convB_kernel<<<(K_DIM * (D_DIM / 2)) / 256, 256>>>(W);

    gemm_hmma<<<dim3(K_DIM / BN, N_ROWS / BM), 256, GEMM_SMEM>>>(
        (const __nv_bfloat16*)pA3, (const __nv_bfloat16*)pB3);

    combine1_kernel<<<(S_DIM * K_DIM) / 256, 256>>>();

    rowpass_kernel<1><<<N_ROWS / RPC, 256>>>(nullptr);
    update_c_kernel<<<(S_DIM * K_DIM) / 256, 256>>>();
    rowpass_kernel<2><<<N_ROWS / RPC, 256>>>(nullptr);
    update_c_kernel<<<(S_DIM * K_DIM) / 256, 256>>>();
    rowpass_kernel<3><<<N_ROWS / RPC, 256>>>(outp);

    if ((long long)out_size > TOT_ELEMS) {
        finalize_kernel<<<1, 1>>>(out + TOT_ELEMS);
    } else if (out_size == 1) {
        finalize_kernel<<<1, 1>>>(out);
    }
}

// round 17
// speedup vs baseline: 1.5332x; 1.0078x over previous
#include <cuda_runtime.h>
#include <cuda_bf16.h>
#include <cuda_fp16.h>
#include <math.h>
#include <stdint.h>

#define S_DIM 4
#define B_DIM 4096
#define D_DIM 768
#define K_DIM 8192
#define N_ROWS 16384
#define RPC 16                  // rows per CTA in row passes
#define TOT_ELEMS 134217728LL   // N_ROWS * K_DIM

#define KTOT 2304               // 3 * D_DIM (concatenated split planes)

// ---------------- scratch (device globals; no allocation allowed) ----------------
__device__ float g_logits[(size_t)N_ROWS * K_DIM];   // 512 MB
__device__ __half g_that[(size_t)N_ROWS * K_DIM];    // 256 MB   t~ (fp16)
__device__ float g_c[S_DIM * K_DIM];                 // c-hat (t~ basis), init 1
__device__ float g_d[S_DIM * K_DIM];                 // shift + ln(A1+eps) - 50
__device__ float g_A[S_DIM * K_DIM];
__device__ float g_r[N_ROWS];
__device__ float g_lse[N_ROWS];
// per-mtile column partials written by the GEMM epilogue: [32 mtiles][S][K]
__device__ float g_part_m[32 * S_DIM * K_DIM];
__device__ float g_part_s[32 * S_DIM * K_DIM];
__device__ float g_loss;

// concatenated bf16 split planes:  A3 = [Ah | Ah | Am],  B3 = [Bh | Bm | Bh]
__device__ __nv_bfloat16 g_A3[(size_t)N_ROWS * KTOT];   // 75.5 MB
__device__ __nv_bfloat16 g_B3[(size_t)K_DIM * KTOT];    // 37.7 MB

// ---------------- helpers ---------------------------------------------------------
__device__ __forceinline__ uint32_t smem_u32(const void* p) {
    uint32_t a;
    asm("{ .reg .u64 t; cvta.to.shared.u64 t, %1; cvt.u32.u64 %0, t; }" : "=r"(a) : "l"(p));
    return a;
}

#define CP_ASYNC16(s, g) \
    asm volatile("cp.async.cg.shared.global [%0], [%1], 16;" :: "r"(s), "l"(g) : "memory")
#define CP_COMMIT() asm volatile("cp.async.commit_group;" ::: "memory")
#define CP_WAIT1()  asm volatile("cp.async.wait_group 1;" ::: "memory")

#define LDMATRIX_X4(r0, r1, r2, r3, addr) \
    asm volatile("ldmatrix.sync.aligned.m8n8.x4.shared.b16 {%0,%1,%2,%3}, [%4];" \
        : "=r"(r0), "=r"(r1), "=r"(r2), "=r"(r3) : "r"(addr))

#define MMA_16816(c0, c1, c2, c3, a0, a1, a2, a3, b0, b1) \
    asm volatile("mma.sync.aligned.m16n8k16.row.col.f32.bf16.bf16.f32 " \
        "{%0,%1,%2,%3}, {%4,%5,%6,%7}, {%8,%9}, {%0,%1,%2,%3};" \
        : "+f"(c0), "+f"(c1), "+f"(c2), "+f"(c3) \
        : "r"(a0), "r"(a1), "r"(a2), "r"(a3), "r"(b0), "r"(b1))

// ---------------- fast exp / log on the FMA pipe ---------------------------------
__device__ __forceinline__ float fast_exp(float x) {
    float t = x * 1.4426950408889634f;
    t = fmaxf(t, -127.0f);
    float n = rintf(t);
    float f = t - n;
    float p = 1.5403530393381609e-4f;
    p = fmaf(p, f, 1.3333558146428443e-3f);
    p = fmaf(p, f, 9.6181291076284772e-3f);
    p = fmaf(p, f, 5.5504108664821580e-2f);
    p = fmaf(p, f, 2.4022650695910072e-1f);
    p = fmaf(p, f, 6.9314718055994531e-1f);
    p = fmaf(p, f, 1.0f);
    return __int_as_float(((int)n + 127) << 23) * p;
}

__device__ __forceinline__ float fast_log(float x) {
    int i = __float_as_int(x);
    int e = ((i >> 23) & 255) - 127;
    float m = __int_as_float((i & 0x007fffff) | 0x3f800000);
    if (m > 1.4142135f) { m *= 0.5f; e++; }
    float u = m - 1.0f;
    float p = -0.125f;
    p = fmaf(p, u, 0.14285714285f);
    p = fmaf(p, u, -0.16666666667f);
    p = fmaf(p, u, 0.2f);
    p = fmaf(p, u, -0.25f);
    p = fmaf(p, u, 0.33333333333f);
    p = fmaf(p, u, -0.5f);
    p = fmaf(p, u, 1.0f);
    p *= u;
    return fmaf((float)e, 0.69314718056f, p);
}

// ---------------- K0: fused norm + A split (warp per row) -------------------------
__global__ void __launch_bounds__(256) convA_kernel(const float* __restrict__ X) {
    const int row = blockIdx.x * 8 + (threadIdx.x >> 5);
    const int lane = threadIdx.x & 31;
    const float4* xr = (const float4*)(X + (size_t)row * D_DIM);
    float4 v[6];
    float ss = 0.f;
    #pragma unroll
    for (int i = 0; i < 6; i++) {
        v[i] = xr[lane + 32 * i];
        ss = fmaf(v[i].x, v[i].x, ss);
        ss = fmaf(v[i].y, v[i].y, ss);
        ss = fmaf(v[i].z, v[i].z, ss);
        ss = fmaf(v[i].w, v[i].w, ss);
    }
    #pragma unroll
    for (int o = 16; o > 0; o >>= 1) ss += __shfl_xor_sync(0xffffffffu, ss, o);
    const float sc = 1.0f / fmaxf(sqrtf(ss), 1e-7f);
    __nv_bfloat16* rowp = g_A3 + (size_t)row * KTOT;
    #pragma unroll
    for (int i = 0; i < 6; i++) {
        const int c4 = 4 * (lane + 32 * i);
        float a0 = v[i].x * sc, a1 = v[i].y * sc, a2 = v[i].z * sc, a3 = v[i].w * sc;
        __nv_bfloat16 h0 = __float2bfloat16(a0), h1 = __float2bfloat16(a1);
        __nv_bfloat16 h2 = __float2bfloat16(a2), h3 = __float2bfloat16(a3);
        __nv_bfloat162 hp0(h0, h1), hp1(h2, h3);
        __nv_bfloat162 mp0(__float2bfloat16(a0 - __bfloat162float(h0)),
                           __float2bfloat16(a1 - __bfloat162float(h1)));
        __nv_bfloat162 mp1(__float2bfloat16(a2 - __bfloat162float(h2)),
                           __float2bfloat16(a3 - __bfloat162float(h3)));
        uint2 hp = make_uint2(*(uint32_t*)&hp0, *(uint32_t*)&hp1);
        uint2 mp = make_uint2(*(uint32_t*)&mp0, *(uint32_t*)&mp1);
        *(uint2*)(rowp + c4)             = hp;
        *(uint2*)(rowp + D_DIM + c4)     = hp;
        *(uint2*)(rowp + 2 * D_DIM + c4) = mp;
    }
}

__global__ void __launch_bounds__(256) convB_kernel(const float* __restrict__ Wm) {
    size_t g = (size_t)blockIdx.x * 256 + threadIdx.x;
    int row = (int)(g / (D_DIM / 2));
    int c2 = (int)(g % (D_DIM / 2)) * 2;
    float2 v = *(const float2*)(Wm + (size_t)row * D_DIM + c2);
    __nv_bfloat16 h0 = __float2bfloat16(v.x);
    __nv_bfloat16 h1 = __float2bfloat16(v.y);
    __nv_bfloat16 m0 = __float2bfloat16(v.x - __bfloat162float(h0));
    __nv_bfloat16 m1 = __float2bfloat16(v.y - __bfloat162float(h1));
    __nv_bfloat16* rowp = g_B3 + (size_t)row * KTOT;
    *(__nv_bfloat162*)(rowp + c2)             = __nv_bfloat162(h0, h1);
    *(__nv_bfloat162*)(rowp + D_DIM + c2)     = __nv_bfloat162(m0, m1);
    *(__nv_bfloat162*)(rowp + 2 * D_DIM + c2) = __nv_bfloat162(h0, h1);
}

// ---------------- K1: HMMA GEMM (bf16x2 split, K=2304) + fused column stats ------
#define BM 128
#define BN 128
#define BKK 64
#define NIT (KTOT / BKK)            // 36
#define RSTR 144
#define STAGE_HALF (128 * RSTR)
#define STAGE_BYTES (2 * STAGE_HALF)
#define NSTAGE 3
#define GEMM_SMEM (NSTAGE * STAGE_BYTES)   // 110592 (2 CTA/SM)

__global__ void __launch_bounds__(256, 2) gemm_hmma(const __nv_bfloat16* __restrict__ A3,
                                                    const __nv_bfloat16* __restrict__ B3) {
    extern __shared__ char smem[];
    const uint32_t sbase = smem_u32(smem);
    const int tid = threadIdx.x;
    const int wid = tid >> 5, lid = tid & 31;
    const int bm = blockIdx.y * BM;
    const int bn = blockIdx.x * BN;
    const int wm = (wid & 1) * 64;
    const int wn = (wid >> 1) * 32;

    const __nv_bfloat16* gA[4];
    const __nv_bfloat16* gB[4];
    uint32_t so[4];
    #pragma unroll
    for (int i = 0; i < 4; i++) {
        const int ch = tid + i * 256;
        const int r = ch >> 3, c = ch & 7;
        gA[i] = A3 + (size_t)(bm + r) * KTOT + c * 8;
        gB[i] = B3 + (size_t)(bn + r) * KTOT + c * 8;
        so[i] = r * RSTR + c * 16;
    }

    const int lrow = (lid & 7) + ((lid >> 3) & 1) * 8;
    const int lkb = ((lid >> 4) & 1) * 16;
    const uint32_t aoff = (uint32_t)(wm + lrow) * RSTR + lkb;
    const uint32_t boff = (uint32_t)(wn + lrow) * RSTR + lkb;

    float acc[4][4][4];
    #pragma unroll
    for (int i = 0; i < 4; i++)
        #pragma unroll
        for (int j = 0; j < 4; j++)
            #pragma unroll
            for (int q = 0; q < 4; q++) acc[i][j][q] = 0.f;

    #pragma unroll
    for (int st = 0; st < 2; st++) {
        const int k0 = st * BKK;
        const uint32_t sa = sbase + st * STAGE_BYTES;
        const uint32_t sb = sa + STAGE_HALF;
        #pragma unroll
        for (int i = 0; i < 4; i++) {
            CP_ASYNC16(sa + so[i], gA[i] + k0);
            CP_ASYNC16(sb + so[i], gB[i] + k0);
        }
        CP_COMMIT();
    }

    int st = 0;
    for (int it = 0; it < NIT; it++) {
        CP_WAIT1();
        __syncthreads();

        if (it + 2 < NIT) {
            const int ps = (st + 2 >= NSTAGE) ? st + 2 - NSTAGE : st + 2;
            const int k0 = (it + 2) * BKK;
            const uint32_t sa = sbase + ps * STAGE_BYTES;
            const uint32_t sb = sa + STAGE_HALF;
            #pragma unroll
            for (int i = 0; i < 4; i++) {
                CP_ASYNC16(sa + so[i], gA[i] + k0);
                CP_ASYNC16(sb + so[i], gB[i] + k0);
            }
        }
        CP_COMMIT();

        const uint32_t sa = sbase + st * STAGE_BYTES;
        const uint32_t sb = sa + STAGE_HALF;
        #pragma unroll
        for (int ks = 0; ks < 4; ks++) {
            uint32_t a[4][4];
            #pragma unroll
            for (int mt = 0; mt < 4; mt++) {
                uint32_t ad = sa + aoff + mt * (16 * RSTR) + ks * 32;
                LDMATRIX_X4(a[mt][0], a[mt][1], a[mt][2], a[mt][3], ad);
            }
            uint32_t b[2][4];
            #pragma unroll
            for (int np = 0; np < 2; np++) {
                uint32_t bd = sb + boff + np * (16 * RSTR) + ks * 32;
                LDMATRIX_X4(b[np][0], b[np][1], b[np][2], b[np][3], bd);
            }
            #pragma unroll
            for (int mt = 0; mt < 4; mt++) {
                #pragma unroll
                for (int nt = 0; nt < 4; nt++) {
                    const int np = nt >> 1, no = nt & 1;
                    MMA_16816(acc[mt][nt][0], acc[mt][nt][1], acc[mt][nt][2], acc[mt][nt][3],
                              a[mt][0], a[mt][1], a[mt][2], a[mt][3],
                              b[np][no], b[np][2 + no]);
                }
            }
        }
        st = (st + 1 == NSTAGE) ? 0 : st + 1;
    }

    // ---- epilogue part 1: per-thread column stats ----
    float cm[8], cs[8];
    #pragma unroll
    for (int nt = 0; nt < 4; nt++) {
        #pragma unroll
        for (int o = 0; o < 2; o++) {
            float mx = -1e30f;
            #pragma unroll
            for (int mt = 0; mt < 4; mt++) {
                mx = fmaxf(mx, acc[mt][nt][o]);
                mx = fmaxf(mx, acc[mt][nt][2 + o]);
            }
            mx *= 20.0f;
            float sm = 0.f;
            #pragma unroll
            for (int mt = 0; mt < 4; mt++) {
                sm += fast_exp(fmaf(acc[mt][nt][o], 20.0f, -mx));
                sm += fast_exp(fmaf(acc[mt][nt][2 + o], 20.0f, -mx));
            }
            cm[nt * 2 + o] = mx;
            cs[nt * 2 + o] = sm;
        }
    }
    #pragma unroll
    for (int off = 4; off <= 16; off <<= 1) {
        #pragma unroll
        for (int i = 0; i < 8; i++) {
            float m2 = __shfl_xor_sync(0xffffffffu, cm[i], off);
            float s2 = __shfl_xor_sync(0xffffffffu, cs[i], off);
            float nm = fmaxf(cm[i], m2);
            cs[i] = cs[i] * fast_exp(cm[i] - nm) + s2 * fast_exp(m2 - nm);
            cm[i] = nm;
        }
    }

    // ---- epilogue part 2: store logits ----
    const int mrow = lid >> 2;
    const int mcol = (lid & 3) * 2;
    #pragma unroll
    for (int mt = 0; mt < 4; mt++) {
        #pragma unroll
        for (int nt = 0; nt < 4; nt++) {
            const int row = bm + wm + mt * 16 + mrow;
            const int col = bn + wn + nt * 8 + mcol;
            float2 v01 = make_float2(acc[mt][nt][0], acc[mt][nt][1]);
            float2 v23 = make_float2(acc[mt][nt][2], acc[mt][nt][3]);
            *(float2*)(g_logits + (size_t)row * K_DIM + col) = v01;
            *(float2*)(g_logits + (size_t)(row + 8) * K_DIM + col) = v23;
        }
    }

    // ---- epilogue part 3: combine the two m-warps, write per-CTA partial ----
    float* sbuf = (float*)smem;
    __syncthreads();
    if ((wid & 1) == 0 && lid < 4) {
        #pragma unroll
        for (int i = 0; i < 8; i++) {
            int c = (wid >> 1) * 32 + (i >> 1) * 8 + lid * 2 + (i & 1);
            sbuf[c * 2] = cm[i];
            sbuf[c * 2 + 1] = cs[i];
        }
    }
    __syncthreads();
    if ((wid & 1) == 1 && lid < 4) {
        const int mt32 = (bm & 4095) >> 7;
        const int sidx = bm >> 12;
        #pragma unroll
        for (int i = 0; i < 8; i++) {
            int c = (wid >> 1) * 32 + (i >> 1) * 8 + lid * 2 + (i & 1);
            float m2 = sbuf[c * 2], s2 = sbuf[c * 2 + 1];
            float nm = fmaxf(cm[i], m2);
            float ns = cs[i] * fast_exp(cm[i] - nm) + s2 * fast_exp(m2 - nm);
            int gidx = (mt32 * S_DIM + sidx) * K_DIM + bn + c;
            g_part_m[gidx] = nm;
            g_part_s[gidx] = ns;
        }
    }
}

// ---------------- K2: combine partials -> d, c=1; zero A -------------------------
__global__ void __launch_bounds__(256) combine1_kernel() {
    const int idx = blockIdx.x * 256 + threadIdx.x;     // s*K + k
    const int s = idx >> 13, k = idx & (K_DIM - 1);
    float m = -1e30f;
    #pragma unroll
    for (int i = 0; i < 32; i++)
        m = fmaxf(m, g_part_m[(i * S_DIM + s) * K_DIM + k]);
    float A = 0.f;
    #pragma unroll
    for (int i = 0; i < 32; i++) {
        const int pi = (i * S_DIM + s) * K_DIM + k;
        A = fmaf(g_part_s[pi], fast_exp(g_part_m[pi] - m), A);
    }
    float A1 = 5.1847055285870724e21f * A;   // * exp(50)
    g_c[idx] = 1.0f;
    g_d[idx] = m + logf(A1 + 1e-8f) - 50.0f;
    g_A[idx] = 0.f;
}

__global__ void __launch_bounds__(256) update_c_kernel() {
    const int idx = blockIdx.x * 256 + threadIdx.x;
    float c = g_c[idx], A = g_A[idx];
    g_c[idx] = c / (c * A + 1e-8f);
    g_A[idx] = 0.f;
    if (idx == 0) g_loss = 0.f;
}

// ---------------- row passes (fp16 smem staging, t~ basis) ------------------------
// element mapping: k = 4*(tid + j*256) + q,  j = 0..7, q = 0..3
// MODE 1: read logits f32x4; t~=exp(20l-d) -> g_that + fp16 stage; branch-free LSE
// MODE 2: read t~ x4; stage fp16; B2 -> r2, A3 partials
// MODE 3: read t~ x4; stage fp16; B3 -> r3, output (re-reads c, L1-hot), loss
template <int MODE>
__global__ void __launch_bounds__(256) rowpass_kernel(float* __restrict__ outp) {
    __shared__ uint2 seb[8 * 256];     // 16 KB fp16 staging (4 halves per entry)
    __shared__ float sA[8], sB[8];
    __shared__ float bcast[1];
    const int tid = threadIdx.x;
    const int warp = tid >> 5, lane = tid & 31;
    const int r0 = blockIdx.x * RPC;
    const int s = r0 >> 12;
    const float4* __restrict__ cv = (const float4*)(g_c + s * K_DIM);
    const float4* __restrict__ dv = (const float4*)(g_d + s * K_DIM);

    float accR[32];
    if (MODE != 3) {
        #pragma unroll
        for (int j = 0; j < 32; j++) accR[j] = 0.f;
    }
    float lossAcc = 0.f;

    for (int rr = 0; rr < RPC; rr++) {
        const int row = r0 + rr;
        const float4* __restrict__ lrow = (const float4*)(g_logits + (size_t)row * K_DIM);
        const uint2* __restrict__ hrow = (const uint2*)(g_that + (size_t)row * K_DIM);
        uint2* __restrict__ hwrow = (uint2*)(g_that + (size_t)row * K_DIM);
        float sumB = 0.f, sumV = 0.f;
        float ls = 0.f;
        #pragma unroll
        for (int j = 0; j < 8; j++) {
            const int k4 = tid + (j << 8);
            if (MODE == 1) {
                float4 l4 = lrow[k4];
                float4 d4 = dv[k4];
                float t0 = fast_exp(fmaf(l4.x, 20.0f, -d4.x));
                float t1 = fast_exp(fmaf(l4.y, 20.0f, -d4.y));
                float t2 = fast_exp(fmaf(l4.z, 20.0f, -d4.z));
                float t3 = fast_exp(fmaf(l4.w, 20.0f, -d4.w));
                sumB += (t0 + t1) + (t2 + t3);
                __half2 h01 = __floats2half2_rn(t0, t1);
                __half2 h23 = __floats2half2_rn(t2, t3);
                uint2 u = make_uint2(*(uint32_t*)&h01, *(uint32_t*)&h23);
                seb[k4] = u;
                hwrow[k4] = u;
                float e0 = fast_exp(l4.x * 8.3333333333333339f);
                float e1 = fast_exp(l4.y * 8.3333333333333339f);
                float e2 = fast_exp(l4.z * 8.3333333333333339f);
                float e3 = fast_exp(l4.w * 8.3333333333333339f);
                ls += (e0 + e1) + (e2 + e3);
            } else if (MODE == 2) {
                uint2 u = hrow[k4];
                float2 f01 = __half22float2(*(__half2*)&u.x);
                float2 f23 = __half22float2(*(__half2*)&u.y);
                float4 c4 = cv[k4];
                sumB = fmaf(f01.x, c4.x, sumB);
                sumB = fmaf(f01.y, c4.y, sumB);
                sumB = fmaf(f23.x, c4.z, sumB);
                sumB = fmaf(f23.y, c4.w, sumB);
                seb[k4] = u;
            } else {
                uint2 u = hrow[k4];
                float2 f01 = __half22float2(*(__half2*)&u.x);
                float2 f23 = __half22float2(*(__half2*)&u.y);
                float4 c4 = cv[k4];
                float4 d4 = dv[k4];
                float th[4] = {f01.x, f01.y, f23.x, f23.y};
                float cc[4] = {c4.x, c4.y, c4.z, c4.w};
                float dd[4] = {d4.x, d4.y, d4.z, d4.w};
                #pragma unroll
                for (int q = 0; q < 4; q++) {
                    float t = th[q] * cc[q];
                    sumB += t;
                    float pred = (fast_log(fmaxf(th[q], 6e-8f)) + dd[q]) * 0.41666666666666669f;
                    sumV = fmaf(t, pred, sumV);
                }
                seb[k4] = u;
            }
        }
        #pragma unroll
        for (int o = 16; o > 0; o >>= 1) {
            sumB += __shfl_xor_sync(0xffffffffu, sumB, o);
            if (MODE == 3) sumV += __shfl_xor_sync(0xffffffffu, sumV, o);
            if (MODE == 1) ls += __shfl_xor_sync(0xffffffffu, ls, o);
        }
        if (lane == 0) {
            sA[warp] = sumB;
            if (MODE == 3) sB[warp] = sumV;
            if (MODE == 1) sB[warp] = ls;
        }
        __syncthreads();
        if (tid == 0) {
            float Bt = 0.f, Vt = 0.f, Lt = 0.f;
            #pragma unroll
            for (int w = 0; w < 8; w++) {
                Bt += sA[w];
                if (MODE == 3) Vt += sB[w];
                if (MODE == 1) Lt += sB[w];
            }
            float rnew;
            if (MODE == 1) {
                rnew = 1.0f / (Bt + 1e-8f);
                g_r[row] = rnew;
                g_lse[row] = logf(Lt);
            } else {
                float rold = g_r[row];
                rnew = rold / (rold * Bt + 1e-8f);
                if (MODE == 2) g_r[row] = rnew;
                if (MODE == 3) lossAcc = fmaf(rnew, g_lse[row] * Bt - Vt, lossAcc);
            }
            bcast[0] = rnew;
        }
        __syncthreads();
        const float rnew = bcast[0];
        if (MODE == 3) {
            float4* orow = (float4*)(outp + (size_t)row * K_DIM);
            #pragma unroll
            for (int j = 0; j < 8; j++) {
                const int k4 = tid + (j << 8);
                uint2 u = seb[k4];
                float2 f01 = __half22float2(*(__half2*)&u.x);
                float2 f23 = __half22float2(*(__half2*)&u.y);
                float4 c4 = cv[k4];
                orow[k4] = make_float4(f01.x * c4.x * rnew, f01.y * c4.y * rnew,
                                       f23.x * c4.z * rnew, f23.y * c4.w * rnew);
            }
        } else {
            #pragma unroll
            for (int j = 0; j < 8; j++) {
                const int k4 = tid + (j << 8);
                uint2 u = seb[k4];
                float2 f01 = __half22float2(*(__half2*)&u.x);
                float2 f23 = __half22float2(*(__half2*)&u.y);
                accR[j * 4 + 0] = fmaf(f01.x, rnew, accR[j * 4 + 0]);
                accR[j * 4 + 1] = fmaf(f01.y, rnew, accR[j * 4 + 1]);
                accR[j * 4 + 2] = fmaf(f23.x, rnew, accR[j * 4 + 2]);
                accR[j * 4 + 3] = fmaf(f23.y, rnew, accR[j * 4 + 3]);
            }
        }
        __syncthreads();
    }

    if (MODE != 3) {
        float* Ag = g_A + s * K_DIM;
        #pragma unroll
        for (int j = 0; j < 8; j++) {
            const int kb = 4 * (tid + (j << 8));
            atomicAdd(&Ag[kb + 0], accR[j * 4 + 0]);
            atomicAdd(&Ag[kb + 1], accR[j * 4 + 1]);
            atomicAdd(&Ag[kb + 2], accR[j * 4 + 2]);
            atomicAdd(&Ag[kb + 3], accR[j * 4 + 3]);
        }
    } else {
        if (tid == 0) atomicAdd(&g_loss, lossAcc);
    }
}

__global__ void finalize_kernel(float* dst) {
    dst[0] = g_loss * (1.0f / 16384.0f);
}

// ---------------- launch ----------------------------------------------------------
extern "C" void kernel_launch(void* const* d_in, const int* in_sizes, int n_in,
                              void* d_out, int out_size) {
    const float* x = (const float*)d_in[0];
    const float* W = (const float*)d_in[1];
    if (n_in >= 2 && in_sizes[0] == K_DIM * D_DIM && in_sizes[1] == N_ROWS * D_DIM) {
        const float* t = x; x = W; W = t;
    }
    float* out = (float*)d_out;

    float* outp = out;
    if ((long long)out_size < TOT_ELEMS) {
        void* p = nullptr;
        cudaGetSymbolAddress(&p, g_logits);
        outp = (float*)p;
    }

    void *pA3, *pB3;
    cudaGetSymbolAddress(&pA3, g_A3);
    cudaGetSymbolAddress(&pB3, g_B3);

    cudaFuncSetAttribute(gemm_hmma, cudaFuncAttributeMaxDynamicSharedMemorySize, GEMM_SMEM);

    convA_kernel<<<N_ROWS / 8, 256>>>(x);
    convB_kernel<<<(K_DIM * (D_DIM / 2)) / 256, 256>>>(W);

    gemm_hmma<<<dim3(K_DIM / BN, N_ROWS / BM), 256, GEMM_SMEM>>>(
        (const __nv_bfloat16*)pA3, (const __nv_bfloat16*)pB3);

    combine1_kernel<<<(S_DIM * K_DIM) / 256, 256>>>();

    rowpass_kernel<1><<<N_ROWS / RPC, 256>>>(nullptr);
    update_c_kernel<<<(S_DIM * K_DIM) / 256, 256>>>();
    rowpass_kernel<2><<<N_ROWS / RPC, 256>>>(nullptr);
    update_c_kernel<<<(S_DIM * K_DIM) / 256, 256>>>();
    rowpass_kernel<3><<<N_ROWS / RPC, 256>>>(outp);

    if ((long long)out_size > TOT_ELEMS) {
        finalize_kernel<<<1, 1>>>(out + TOT_ELEMS);
    } else if (out_size == 1) {
        finalize_kernel<<<1, 1>>>(out);
    }
}